// round 8
// baseline (speedup 1.0000x reference)
#include <cuda_runtime.h>

#define NB 4
#define LL 4096
#define ND 8
#define KMAX 64
#define NCODES 256
#define NBLK 128
#define BIGV 65535

// Scratch (no allocations). All counters zero-initialized and self-reset each
// run -> deterministic across graph replays.
__device__ float          g_rows [NB * NCODES * KMAX];   // 256 KB
__device__ int            g_cnt  [NB * NCODES];          // 4 KB
__device__ unsigned short g_tmp  [NB * NCODES * KMAX];   // 128 KB buckets
__device__ unsigned char  g_codes[NB * LL];              // 16 KB (overflow path)
__device__ int g_sdone, g_rdone, g_edone;

__device__ __forceinline__ int pack8(float4 a, float4 c) {
    return (a.x > 0.f)        | ((a.y > 0.f) << 1) |
           ((a.z > 0.f) << 2) | ((a.w > 0.f) << 3) |
           ((c.x > 0.f) << 4) | ((c.y > 0.f) << 5) |
           ((c.z > 0.f) << 6) | ((c.w > 0.f) << 7);
}

// Gate: block-arrive (atomicAdd) then 1 thread polls with volatile L2 loads
// (NOT atomic RMW spam - that was round 6's failure mode).
__device__ __forceinline__ void grid_gate(int* ctr) {
    __syncthreads();
    if (threadIdx.x == 0) {
        __threadfence();                       // release my writes
        atomicAdd(ctr, 1);
        while (*(volatile int*)ctr < NBLK) __nanosleep(64);
        __threadfence();                       // acquire others' writes
    }
    __syncthreads();
}

__global__ void __launch_bounds__(256, 2)
k_all(const float* __restrict__ key_up,
      const float* __restrict__ query_up,
      float* __restrict__ out) {
    int tid  = threadIdx.x;
    int b    = blockIdx.x;
    int warp = tid >> 5;
    int lane = tid & 31;
    int gw   = b * 8 + warp;                   // 0..1023

    // ---- Prefetch phase-C query + code (overlaps phases A/B) ----
    float4 q = reinterpret_cast<const float4*>(query_up)[b * 256 + tid];
    int nib = (q.x > 0.f)        | ((q.y > 0.f) << 1) |
              ((q.z > 0.f) << 2) | ((q.w > 0.f) << 3);
    int pr  = __shfl_xor_sync(0xffffffffu, nib, 1);
    int code_q = (lane & 1) ? (pr | (nib << 4)) : (nib | (pr << 4));
    int qi = gw * 16 + (lane >> 1);            // query id (each by 2 lanes)

    // ---- Phase A: scatter 128 keys per block into (batch,code) buckets ----
    if (tid < 128) {
        int t = b * 128 + tid;                 // key id 0..16383
        const float4* kp = reinterpret_cast<const float4*>(key_up) + t * 2;
        int code = pack8(kp[0], kp[1]);
        g_codes[t] = (unsigned char)code;
        int cidx = ((t >> 12) << 8) | code;
        int pos = atomicAdd(&g_cnt[cidx], 1);
        if (pos < KMAX) g_tmp[cidx * KMAX + pos] = (unsigned short)(t & (LL - 1));
    }
    grid_gate(&g_sdone);

    // ---- Phase B: one warp per (batch,code): rank-sort bucket into row ----
    {
        int n = g_cnt[gw];
        float* row = g_rows + gw * KMAX;
        if (n <= KMAX) {
            int v0 = (lane      < n) ? (int)g_tmp[gw * KMAX + lane]      : BIGV;
            int v1 = (lane + 32 < n) ? (int)g_tmp[gw * KMAX + lane + 32] : BIGV;
            int r0 = 0, r1 = 0;
            #pragma unroll
            for (int k = 0; k < 32; k++) {
                int u0 = __shfl_sync(0xffffffffu, v0, k);
                int u1 = __shfl_sync(0xffffffffu, v1, k);
                r0 += (u0 < v0) + (u1 < v0);
                r1 += (u0 < v1) + (u1 < v1);
            }
            int pad = KMAX - n;                // disjoint targets, no syncs
            if (lane      < pad) row[lane]      = -1.0f;
            if (lane + 32 < pad) row[lane + 32] = -1.0f;
            if (v0 != BIGV) row[pad + r0] = (float)v0;
            if (v1 != BIGV) row[pad + r1] = (float)v1;
        } else {
            // >64 matches (stat. impossible, guarded): stable ballot scan.
            int bb = gw >> 8, c = gw & 255;
            const uchar4* cc = reinterpret_cast<const uchar4*>(g_codes + bb * LL);
            unsigned lt = (1u << lane) - 1u;
            int m = 0;
            for (int r = 0; r < 32 && m < KMAX; r++) {
                uchar4 v = cc[r * 32 + lane];
                unsigned m0 = __ballot_sync(0xffffffffu, v.x == c);
                unsigned m1 = __ballot_sync(0xffffffffu, v.y == c);
                unsigned m2 = __ballot_sync(0xffffffffu, v.z == c);
                unsigned m3 = __ballot_sync(0xffffffffu, v.w == c);
                int p = m + __popc(m0 & lt) + __popc(m1 & lt)
                          + __popc(m2 & lt) + __popc(m3 & lt);
                int j0 = (r * 32 + lane) * 4;
                if (v.x == c) { if (p < KMAX) row[p] = (float)j0;       p++; }
                if (v.y == c) { if (p < KMAX) row[p] = (float)(j0 + 1); p++; }
                if (v.z == c) { if (p < KMAX) row[p] = (float)(j0 + 2); p++; }
                if (v.w == c) { if (p < KMAX) row[p] = (float)(j0 + 3); p++; }
                m += __popc(m0) + __popc(m1) + __popc(m2) + __popc(m3);
            }
        }
        if (lane == 0) g_cnt[gw] = 0;          // self-reset for next replay
    }
    grid_gate(&g_rdone);

    // ---- Phase C: emit. Each lane copies half of one 256B row ----
    {
        int bq = gw >> 8;
        int h  = (lane & 1) << 3;
        const float4* src = reinterpret_cast<const float4*>(g_rows)
                            + ((bq << 8) + code_q) * 16 + h;
        float4* dst = reinterpret_cast<float4*>(out) + qi * 16 + h;
        float4 v[8];
        #pragma unroll
        for (int t = 0; t < 8; t++) v[t] = src[t];
        #pragma unroll
        for (int t = 0; t < 8; t++) dst[t] = v[t];
    }

    // ---- Reset gate counters (last block; all gates already passed) ----
    if (tid == 0) {
        int d = atomicAdd(&g_edone, 1);
        if (d == NBLK - 1) { g_edone = 0; g_sdone = 0; g_rdone = 0; }
    }
}

extern "C" void kernel_launch(void* const* d_in, const int* in_sizes, int n_in,
                              void* d_out, int out_size) {
    // Identify inputs by element count (robust to metadata ordering).
    const float* query_up = nullptr;
    const float* key_up   = nullptr;
    for (int i = 0; i < n_in; i++) {
        if (in_sizes[i] == NB * LL * ND) {
            if (!query_up)      query_up = (const float*)d_in[i];
            else if (!key_up)   key_up   = (const float*)d_in[i];
        }
    }
    if (!query_up || !key_up) {
        query_up = (const float*)d_in[0];
        key_up   = (const float*)d_in[1];
    }
    float* out = (float*)d_out;

    k_all<<<NBLK, 256>>>(key_up, query_up, out);
}

// round 9
// speedup vs baseline: 1.3403x; 1.3403x over previous
#include <cuda_runtime.h>

#define NB 4
#define LL 4096
#define ND 8
#define KMAX 64
#define NCODES 256
#define BIGV 65535

// Scratch (no allocations). g_cnt zero-initialized; reset by k_rank each run
// (exactly one warp owns each counter) -> deterministic across graph replays.
__device__ float          g_rows  [NB * NCODES * KMAX];  // 256 KB
__device__ int            g_cnt   [NB * NCODES];         // 4 KB
__device__ unsigned short g_tmp   [NB * NCODES * KMAX];  // 128 KB buckets
__device__ unsigned char  g_codes [NB * LL];             // 16 KB key codes
__device__ unsigned char  g_qcodes[NB * LL];             // 16 KB query codes

__device__ __forceinline__ int pack8(float4 a, float4 c) {
    return (a.x > 0.f)        | ((a.y > 0.f) << 1) |
           ((a.z > 0.f) << 2) | ((a.w > 0.f) << 3) |
           ((c.x > 0.f) << 4) | ((c.y > 0.f) << 5) |
           ((c.z > 0.f) << 6) | ((c.w > 0.f) << 7);
}

// K1: 32K threads. Blocks 0..63: scatter keys into (batch,code) buckets.
// Blocks 64..127: pack query codes into g_qcodes.
__global__ void k_prep(const float* __restrict__ key_up,
                       const float* __restrict__ query_up) {
    int tid = threadIdx.x;
    if (blockIdx.x < 64) {
        int t = blockIdx.x * 256 + tid;                  // key id 0..16383
        const float4* p = reinterpret_cast<const float4*>(key_up) + t * 2;
        int code = pack8(p[0], p[1]);
        g_codes[t] = (unsigned char)code;
        int cidx = ((t >> 12) << 8) | code;
        int pos = atomicAdd(&g_cnt[cidx], 1);
        if (pos < KMAX) g_tmp[cidx * KMAX + pos] = (unsigned short)(t & (LL - 1));
    } else {
        int t = (blockIdx.x - 64) * 256 + tid;           // query id 0..16383
        const float4* p = reinterpret_cast<const float4*>(query_up) + t * 2;
        g_qcodes[t] = (unsigned char)pack8(p[0], p[1]);
    }
}

// K2: one warp per (batch,code). Rank-sort <=64 bucket entries (distinct j,
// arbitrary arrival order) into the padded ascending row; reset the counter.
__global__ void k_rank() {
    int gw   = (blockIdx.x * blockDim.x + threadIdx.x) >> 5;  // 0..1023 = cidx
    int lane = threadIdx.x & 31;
    int n    = g_cnt[gw];
    float* row = g_rows + gw * KMAX;

    if (n <= KMAX) {
        int v0 = (lane      < n) ? (int)g_tmp[gw * KMAX + lane]      : BIGV;
        int v1 = (lane + 32 < n) ? (int)g_tmp[gw * KMAX + lane + 32] : BIGV;
        int r0 = 0, r1 = 0;
        #pragma unroll
        for (int k = 0; k < 32; k++) {
            int u0 = __shfl_sync(0xffffffffu, v0, k);
            int u1 = __shfl_sync(0xffffffffu, v1, k);
            r0 += (u0 < v0) + (u1 < v0);
            r1 += (u0 < v1) + (u1 < v1);
        }
        int pad = KMAX - n;              // disjoint targets, no syncs needed
        if (lane      < pad) row[lane]      = -1.0f;
        if (lane + 32 < pad) row[lane + 32] = -1.0f;
        if (v0 != BIGV) row[pad + r0] = (float)v0;
        if (v1 != BIGV) row[pad + r1] = (float)v1;
    } else {
        // >64 matches (stat. impossible for sign codes, guarded): stable scan.
        int b = gw >> 8, c = gw & 255;
        const uchar4* cc = reinterpret_cast<const uchar4*>(g_codes + b * LL);
        unsigned lt = (1u << lane) - 1u;
        int m = 0;
        for (int r = 0; r < 32 && m < KMAX; r++) {
            uchar4 v = cc[r * 32 + lane];
            unsigned m0 = __ballot_sync(0xffffffffu, v.x == c);
            unsigned m1 = __ballot_sync(0xffffffffu, v.y == c);
            unsigned m2 = __ballot_sync(0xffffffffu, v.z == c);
            unsigned m3 = __ballot_sync(0xffffffffu, v.w == c);
            int p = m + __popc(m0 & lt) + __popc(m1 & lt)
                      + __popc(m2 & lt) + __popc(m3 & lt);
            int j0 = (r * 32 + lane) * 4;
            if (v.x == c) { if (p < KMAX) row[p] = (float)j0;       p++; }
            if (v.y == c) { if (p < KMAX) row[p] = (float)(j0 + 1); p++; }
            if (v.z == c) { if (p < KMAX) row[p] = (float)(j0 + 2); p++; }
            if (v.w == c) { if (p < KMAX) row[p] = (float)(j0 + 3); p++; }
            m += __popc(m0) + __popc(m1) + __popc(m2) + __popc(m3);
        }
    }
    if (lane == 0) g_cnt[gw] = 0;        // self-reset for next graph replay
}

// K3: flat streaming copy, one output float4 per thread (262,144 threads).
// code byte is L1-broadcast (16 threads share), row float4 from L2-hot g_rows,
// store fully coalesced to DRAM.
__global__ void k_emit(float* __restrict__ out) {
    int i  = blockIdx.x * blockDim.x + threadIdx.x;      // 0..262143
    int qi = i >> 4;                                     // query id
    int k  = i & 15;                                     // float4 within row
    int b  = qi >> 12;
    int code = (int)g_qcodes[qi];
    reinterpret_cast<float4*>(out)[i] =
        reinterpret_cast<const float4*>(g_rows)[(((b << 8) + code) << 4) + k];
}

extern "C" void kernel_launch(void* const* d_in, const int* in_sizes, int n_in,
                              void* d_out, int out_size) {
    // Identify inputs by element count (robust to metadata ordering).
    const float* query_up = nullptr;
    const float* key_up   = nullptr;
    for (int i = 0; i < n_in; i++) {
        if (in_sizes[i] == NB * LL * ND) {
            if (!query_up)      query_up = (const float*)d_in[i];
            else if (!key_up)   key_up   = (const float*)d_in[i];
        }
    }
    if (!query_up || !key_up) {
        query_up = (const float*)d_in[0];
        key_up   = (const float*)d_in[1];
    }
    float* out = (float*)d_out;

    k_prep<<<128, 256>>>(key_up, query_up);  // 32K threads
    k_rank<<<256, 128>>>();                  // 1024 warps, 256 blocks
    k_emit<<<1024, 256>>>(out);              // 262,144 threads, 1 float4 each
}